// round 9
// baseline (speedup 1.0000x reference)
#include <cuda_runtime.h>
#include <cuda_fp16.h>

// ---------------------------------------------------------------------------
// 3-layer GCN. R9: GEMM retiled BM=128 -> BM=64 (WARPS 2x4) to cut acc regs
// 64->32/thread and force 2 CTAs/SM (__launch_bounds__(256,2)). R8 ncu showed
// occ=12.5% (1 CTA/SM), issue=26%, tensor=30% on gemm1 -- occupancy is the
// binding constraint, and A-traffic is unchanged by this split.
// ---------------------------------------------------------------------------

#define NN 100000
#define NE 1600000
#define IN_C 256
#define H1C 128
#define H2C 64
#define OUTC 32

__device__ int    g_cnt[NN];
__device__ int    g_cursor[NN];
__device__ int    g_off[NN];
__device__ int    g_bsum[128];
__device__ int    g_boff[128];
__device__ float  g_dis[NN];
__device__ int    g_esrc[NE];
__device__ float  g_enorm[NE];
__device__ __half g_h[(size_t)NN * 128];   // transformed features, fp16
__device__ float4 g_a4[(size_t)NN * 32];   // aggregated features, fp32

// ---------------------------------------------------------------------------
// graph preprocessing
// ---------------------------------------------------------------------------
__global__ void k_zero(int n) {
    int i = blockIdx.x * blockDim.x + threadIdx.x;
    if (i < n) g_cnt[i] = 0;
}

__global__ void k_count(const int* __restrict__ col, int e_cnt) {
    int e = blockIdx.x * blockDim.x + threadIdx.x;
    if (e < e_cnt) atomicAdd(&g_cnt[col[e]], 1);
}

// scan1 + dis fused
__global__ void k_scan1(int n) {
    __shared__ int s[1024];
    int i = blockIdx.x * 1024 + threadIdx.x;
    int v = (i < n) ? g_cnt[i] : 0;
    if (i < n) g_dis[i] = rsqrtf((float)v + 1.0f);
    s[threadIdx.x] = v;
    __syncthreads();
    #pragma unroll
    for (int off = 1; off < 1024; off <<= 1) {
        int t = (threadIdx.x >= off) ? s[threadIdx.x - off] : 0;
        __syncthreads();
        s[threadIdx.x] += t;
        __syncthreads();
    }
    if (i < n) g_off[i] = s[threadIdx.x];
    if (threadIdx.x == 1023) g_bsum[blockIdx.x] = s[1023];
}

__global__ void k_scan2(int nb) {
    if (blockIdx.x == 0 && threadIdx.x == 0) {
        int run = 0;
        for (int b = 0; b < nb; b++) { g_boff[b] = run; run += g_bsum[b]; }
    }
}

__global__ void k_scan3(int n) {
    int i = blockIdx.x * blockDim.x + threadIdx.x;
    if (i < n) {
        int off = g_off[i] - g_cnt[i] + g_boff[i >> 10];
        g_off[i] = off;
        g_cursor[i] = off;
    }
}

__global__ void k_scatter(const int* __restrict__ row, const int* __restrict__ col, int e_cnt) {
    int e = blockIdx.x * blockDim.x + threadIdx.x;
    if (e >= e_cnt) return;
    int r = row[e], c = col[e];
    int pos = atomicAdd(&g_cursor[c], 1);
    g_esrc[pos]  = r;
    g_enorm[pos] = g_dis[r] * g_dis[c];
}

// ---------------------------------------------------------------------------
// single-pass tf32 GEMM, BM=64, 2 CTAs/SM:  C = A @ W, fp16 output
// ---------------------------------------------------------------------------
__device__ __forceinline__ unsigned f2tf(float f) {
    unsigned r;
    asm("cvt.rna.tf32.f32 %0, %1;" : "=r"(r) : "f"(f));
    return r;
}

__device__ __forceinline__ void mma_tf32(float* c, const unsigned* a, const unsigned* b) {
    asm volatile(
        "mma.sync.aligned.m16n8k8.row.col.f32.tf32.tf32.f32 "
        "{%0,%1,%2,%3},{%4,%5,%6,%7},{%8,%9},{%0,%1,%2,%3};"
        : "+f"(c[0]), "+f"(c[1]), "+f"(c[2]), "+f"(c[3])
        : "r"(a[0]), "r"(a[1]), "r"(a[2]), "r"(a[3]), "r"(b[0]), "r"(b[1]));
}

template <int N, int K>
__launch_bounds__(256, 2)
__global__ void k_gemm_tc(const float* __restrict__ A, const float* __restrict__ W,
                          __half* __restrict__ C, int M) {
    constexpr int BM = 64, BK = 32;
    constexpr int WARPS_M = 2, WARPS_N = 4;
    constexpr int WM = BM / WARPS_M;   // 32
    constexpr int WN = N / WARPS_N;    // 32 / 16 / 8
    constexpr int MT = WM / 16;        // 2
    constexpr int NT = WN / 8;         // 4 / 2 / 1
    constexpr int ASTRIDE = BK + 4;
    constexpr int BSTRIDE = N + 4;
    constexpr int AREG = BM * BK / 4 / 256;    // 2
    constexpr int WREG = (BK * N / 4) / 256;   // 4 / 2 / 1

    __shared__ unsigned As[BM * ASTRIDE];
    __shared__ unsigned Ws[BK * BSTRIDE];

    int tid = threadIdx.x;
    int lane = tid & 31, warp = tid >> 5;
    int wm = (warp & 1) * WM;
    int wn = (warp >> 1) * WN;
    int m0 = blockIdx.x * BM;
    int g = lane >> 2, tg = lane & 3;

    float acc[MT][NT][4] = {};
    float4 aReg[AREG];
    float4 wReg[WREG];

    int a_r[AREG], a_c4[AREG];
    #pragma unroll
    for (int i = 0; i < AREG; i++) {
        int idx = tid + i * 256;
        a_r[i] = idx >> 3;
        a_c4[i] = idx & 7;
    }
    int w_r[WREG], w_c4[WREG];
    #pragma unroll
    for (int i = 0; i < WREG; i++) {
        int idx = tid + i * 256;
        w_r[i] = idx / (N / 4);
        w_c4[i] = idx % (N / 4);
    }

    // prefetch tile 0
    #pragma unroll
    for (int i = 0; i < AREG; i++) {
        int m = m0 + a_r[i];
        aReg[i] = make_float4(0.f, 0.f, 0.f, 0.f);
        if (m < M)
            aReg[i] = *reinterpret_cast<const float4*>(A + (size_t)m * K + a_c4[i] * 4);
    }
    #pragma unroll
    for (int i = 0; i < WREG; i++)
        wReg[i] = *reinterpret_cast<const float4*>(W + (size_t)w_r[i] * N + w_c4[i] * 4);

    for (int k0 = 0; k0 < K; k0 += BK) {
        #pragma unroll
        for (int i = 0; i < AREG; i++) {
            uint4 u = make_uint4(f2tf(aReg[i].x), f2tf(aReg[i].y),
                                 f2tf(aReg[i].z), f2tf(aReg[i].w));
            *reinterpret_cast<uint4*>(As + a_r[i] * ASTRIDE + a_c4[i] * 4) = u;
        }
        #pragma unroll
        for (int i = 0; i < WREG; i++) {
            uint4 u = make_uint4(f2tf(wReg[i].x), f2tf(wReg[i].y),
                                 f2tf(wReg[i].z), f2tf(wReg[i].w));
            *reinterpret_cast<uint4*>(Ws + w_r[i] * BSTRIDE + w_c4[i] * 4) = u;
        }
        __syncthreads();

        int kn = k0 + BK;
        if (kn < K) {
            #pragma unroll
            for (int i = 0; i < AREG; i++) {
                int m = m0 + a_r[i];
                aReg[i] = make_float4(0.f, 0.f, 0.f, 0.f);
                if (m < M)
                    aReg[i] = *reinterpret_cast<const float4*>(A + (size_t)m * K + kn + a_c4[i] * 4);
            }
            #pragma unroll
            for (int i = 0; i < WREG; i++)
                wReg[i] = *reinterpret_cast<const float4*>(W + (size_t)(kn + w_r[i]) * N + w_c4[i] * 4);
        }

        #pragma unroll
        for (int kk = 0; kk < BK; kk += 8) {
            unsigned a[MT][4];
            #pragma unroll
            for (int mt = 0; mt < MT; mt++) {
                #pragma unroll
                for (int j = 0; j < 4; j++) {
                    int row = wm + mt * 16 + g + (j & 1) * 8;
                    int col = kk + tg + (j >> 1) * 4;
                    a[mt][j] = As[row * ASTRIDE + col];
                }
            }
            #pragma unroll
            for (int nt = 0; nt < NT; nt++) {
                unsigned b[2];
                #pragma unroll
                for (int j = 0; j < 2; j++) {
                    int kr = kk + tg + j * 4;
                    int col = wn + nt * 8 + g;
                    b[j] = Ws[kr * BSTRIDE + col];
                }
                #pragma unroll
                for (int mt = 0; mt < MT; mt++)
                    mma_tf32(acc[mt][nt], a[mt], b);
            }
        }
        __syncthreads();
    }

    #pragma unroll
    for (int mt = 0; mt < MT; mt++) {
        #pragma unroll
        for (int nt = 0; nt < NT; nt++) {
            int row0 = m0 + wm + mt * 16 + g;
            int col = wn + nt * 8 + 2 * tg;
            if (row0 < M)
                *reinterpret_cast<__half2*>(C + (size_t)row0 * N + col) =
                    __floats2half2_rn(acc[mt][nt][0], acc[mt][nt][1]);
            int row1 = row0 + 8;
            if (row1 < M)
                *reinterpret_cast<__half2*>(C + (size_t)row1 * N + col) =
                    __floats2half2_rn(acc[mt][nt][2], acc[mt][nt][3]);
        }
    }
}

// ---------------------------------------------------------------------------
// aggregation: warp per node; fp16 gathers, fp32 accumulate
// ---------------------------------------------------------------------------
template <int VEC>
__device__ __forceinline__ void loadh(float* d, const __half* __restrict__ p) {
    if constexpr (VEC == 4) {
        uint2 raw = __ldg(reinterpret_cast<const uint2*>(p));
        float2 a = __half22float2(*reinterpret_cast<const __half2*>(&raw.x));
        float2 b = __half22float2(*reinterpret_cast<const __half2*>(&raw.y));
        d[0] = a.x; d[1] = a.y; d[2] = b.x; d[3] = b.y;
    } else if constexpr (VEC == 2) {
        __half2 h2 = __ldg(reinterpret_cast<const __half2*>(p));
        float2 a = __half22float2(h2);
        d[0] = a.x; d[1] = a.y;
    } else {
        d[0] = __half2float(__ldg(p));
    }
}

template <int F, bool RELU>
__launch_bounds__(256)
__global__ void k_agg(const __half* __restrict__ h, const float* __restrict__ bias,
                      float* __restrict__ out) {
    constexpr int VEC = F / 32;
    int node = (blockIdx.x * blockDim.x + threadIdx.x) >> 5;
    int lane = threadIdx.x & 31;
    if (node >= NN) return;

    float acc[VEC];
    {
        float d = g_dis[node];
        float ns = d * d;
        float t[VEC];
        loadh<VEC>(t, h + (size_t)node * F + lane * VEC);
        #pragma unroll
        for (int v = 0; v < VEC; v++) acc[v] = ns * t[v];
    }

    int start = g_off[node];
    int cnt   = g_cnt[node];
    int e = start, end = start + cnt;

    for (; e + 8 <= end; e += 8) {
        int   s[8];
        float nm[8];
        #pragma unroll
        for (int j = 0; j < 8; j++) { s[j] = g_esrc[e + j]; nm[j] = g_enorm[e + j]; }
        float t[8][VEC];
        #pragma unroll
        for (int j = 0; j < 8; j++)
            loadh<VEC>(t[j], h + (size_t)s[j] * F + lane * VEC);
        #pragma unroll
        for (int j = 0; j < 8; j++)
            #pragma unroll
            for (int v = 0; v < VEC; v++) acc[v] += nm[j] * t[j][v];
    }
    for (; e + 4 <= end; e += 4) {
        int   s[4];
        float nm[4];
        #pragma unroll
        for (int j = 0; j < 4; j++) { s[j] = g_esrc[e + j]; nm[j] = g_enorm[e + j]; }
        float t[4][VEC];
        #pragma unroll
        for (int j = 0; j < 4; j++)
            loadh<VEC>(t[j], h + (size_t)s[j] * F + lane * VEC);
        #pragma unroll
        for (int j = 0; j < 4; j++)
            #pragma unroll
            for (int v = 0; v < VEC; v++) acc[v] += nm[j] * t[j][v];
    }
    for (; e < end; e++) {
        int s0 = g_esrc[e];
        float nm = g_enorm[e];
        float t[VEC];
        loadh<VEC>(t, h + (size_t)s0 * F + lane * VEC);
        #pragma unroll
        for (int v = 0; v < VEC; v++) acc[v] += nm * t[v];
    }

    float res[VEC];
    #pragma unroll
    for (int v = 0; v < VEC; v++) {
        float r = acc[v] + bias[lane * VEC + v];
        if (RELU) r = fmaxf(r, 0.0f);
        res[v] = r;
    }
    float* op = out + (size_t)node * F + lane * VEC;
    if constexpr (VEC == 4)      *reinterpret_cast<float4*>(op) = make_float4(res[0], res[1], res[2], res[3]);
    else if constexpr (VEC == 2) *reinterpret_cast<float2*>(op) = make_float2(res[0], res[1]);
    else                         *op = res[0];
}

// ---------------------------------------------------------------------------
extern "C" void kernel_launch(void* const* d_in, const int* in_sizes, int n_in,
                              void* d_out, int out_size) {
    const float* x  = (const float*)d_in[0];
    const int*   ei = (const int*)d_in[1];
    const float* W1 = (const float*)d_in[2];
    const float* b1 = (const float*)d_in[3];
    const float* W2 = (const float*)d_in[4];
    const float* b2 = (const float*)d_in[5];
    const float* W3 = (const float*)d_in[6];
    const float* b3 = (const float*)d_in[7];

    int M = in_sizes[0] / IN_C;   // 100000
    int E = in_sizes[1] / 2;      // 1600000
    const int* row = ei;          // sources
    const int* col = ei + E;      // targets
    float* out = (float*)d_out;

    __half* gh;
    float*  ga;
    cudaGetSymbolAddress((void**)&gh, g_h);
    cudaGetSymbolAddress((void**)&ga, g_a4);

    int nb1024 = (M + 1023) / 1024;
    int aggBlocks = (M + 7) / 8;
    int gemmBlocks = (M + 63) / 64;

    // gemm1 kept in launch slot 4 for the ncu window
    k_zero   <<<(M + 255) / 256, 256>>>(M);                       // 1
    k_count  <<<(E + 255) / 256, 256>>>(col, E);                  // 2
    k_scan1  <<<nb1024, 1024>>>(M);                               // 3
    k_gemm_tc<H1C, IN_C><<<gemmBlocks, 256>>>(x, W1, gh, M);      // 4 <- profiled
    k_scan2  <<<1, 32>>>(nb1024);                                 // 5
    k_scan3  <<<(M + 255) / 256, 256>>>(M);                       // 6
    k_scatter<<<(E + 255) / 256, 256>>>(row, col, E);             // 7

    k_agg<H1C, true><<<aggBlocks, 256>>>(gh, b1, ga);

    k_gemm_tc<H2C, H1C><<<gemmBlocks, 256>>>(ga, W2, gh, M);
    k_agg<H2C, true><<<aggBlocks, 256>>>(gh, b2, ga);

    k_gemm_tc<OUTC, H2C><<<gemmBlocks, 256>>>(ga, W3, gh, M);
    k_agg<OUTC, false><<<aggBlocks, 256>>>(gh, b3, out);
}

// round 10
// speedup vs baseline: 1.0917x; 1.0917x over previous
#include <cuda_runtime.h>
#include <cuda_fp16.h>

// ---------------------------------------------------------------------------
// 3-layer GCN. R10: GEMM datapath = single-pass fp16 mma.m16n8k16 (same
// 10-bit mantissa as tf32 -> same error class), halving L1 bytes/MAC, smem
// footprint and tensor instruction count vs R7/R9 tf32. Conversion hoisted to
// smem store (__floats2half2_rn). Agg writes fp16 for layers 1-2 (replaces
// the STS-time rounding; halves agg-write + gemm2/3 LDG traffic).
// R9 evidence: L1-throughput-bound (77%), occupancy not binding.
// ---------------------------------------------------------------------------

#define NN 100000
#define NE 1600000
#define IN_C 256
#define H1C 128
#define H2C 64
#define OUTC 32

__device__ int    g_cnt[NN];
__device__ int    g_cursor[NN];
__device__ int    g_off[NN];
__device__ int    g_bsum[128];
__device__ int    g_boff[128];
__device__ float  g_dis[NN];
__device__ int    g_esrc[NE];
__device__ float  g_enorm[NE];
__device__ __half g_h[(size_t)NN * 128];   // GEMM outputs (fp16)
__device__ __half g_a[(size_t)NN * 128];   // agg outputs (fp16, layers 1-2)

// ---------------------------------------------------------------------------
// graph preprocessing
// ---------------------------------------------------------------------------
__global__ void k_zero(int n) {
    int i = blockIdx.x * blockDim.x + threadIdx.x;
    if (i < n) g_cnt[i] = 0;
}

__global__ void k_count(const int* __restrict__ col, int e_cnt) {
    int e = blockIdx.x * blockDim.x + threadIdx.x;
    if (e < e_cnt) atomicAdd(&g_cnt[col[e]], 1);
}

__global__ void k_scan1(int n) {
    __shared__ int s[1024];
    int i = blockIdx.x * 1024 + threadIdx.x;
    int v = (i < n) ? g_cnt[i] : 0;
    if (i < n) g_dis[i] = rsqrtf((float)v + 1.0f);
    s[threadIdx.x] = v;
    __syncthreads();
    #pragma unroll
    for (int off = 1; off < 1024; off <<= 1) {
        int t = (threadIdx.x >= off) ? s[threadIdx.x - off] : 0;
        __syncthreads();
        s[threadIdx.x] += t;
        __syncthreads();
    }
    if (i < n) g_off[i] = s[threadIdx.x];
    if (threadIdx.x == 1023) g_bsum[blockIdx.x] = s[1023];
}

__global__ void k_scan2(int nb) {
    if (blockIdx.x == 0 && threadIdx.x == 0) {
        int run = 0;
        for (int b = 0; b < nb; b++) { g_boff[b] = run; run += g_bsum[b]; }
    }
}

__global__ void k_scan3(int n) {
    int i = blockIdx.x * blockDim.x + threadIdx.x;
    if (i < n) {
        int off = g_off[i] - g_cnt[i] + g_boff[i >> 10];
        g_off[i] = off;
        g_cursor[i] = off;
    }
}

__global__ void k_scatter(const int* __restrict__ row, const int* __restrict__ col, int e_cnt) {
    int e = blockIdx.x * blockDim.x + threadIdx.x;
    if (e >= e_cnt) return;
    int r = row[e], c = col[e];
    int pos = atomicAdd(&g_cursor[c], 1);
    g_esrc[pos]  = r;
    g_enorm[pos] = g_dis[r] * g_dis[c];
}

// ---------------------------------------------------------------------------
// single-pass fp16 GEMM:  C[M,N] = A[M,K] @ W[K,N], fp16 out, fp32 acc.
// A input is fp32 (layer 1) or fp16 (layers 2,3). W always fp32.
// ---------------------------------------------------------------------------
__device__ __forceinline__ void mma_f16(float* c, const unsigned* a, const unsigned* b) {
    asm volatile(
        "mma.sync.aligned.m16n8k16.row.col.f32.f16.f16.f32 "
        "{%0,%1,%2,%3},{%4,%5,%6,%7},{%8,%9},{%0,%1,%2,%3};"
        : "+f"(c[0]), "+f"(c[1]), "+f"(c[2]), "+f"(c[3])
        : "r"(a[0]), "r"(a[1]), "r"(a[2]), "r"(a[3]), "r"(b[0]), "r"(b[1]));
}

template <typename AT, int N, int K>
__launch_bounds__(256, 2)
__global__ void k_gemm(const AT* __restrict__ A, const float* __restrict__ W,
                       __half* __restrict__ C, int M) {
    constexpr bool A16 = (sizeof(AT) == 2);
    constexpr int BM = 64, BK = 32;
    constexpr int SA = BK + 8;         // 40 halves: conflict-free frag loads
    constexpr int SW = BK + 4;         // 36 halves: conflict-free half2 stores
    constexpr int WM = 32;             // 2 warps in M
    constexpr int WN = N / 4;          // 4 warps in N: 32 / 16 / 8
    constexpr int MT = 2;
    constexpr int NT = WN / 8;         // 4 / 2 / 1
    constexpr int KSTEP = 256 / N;     // W loader k2 stride
    constexpr int WITER = (BK / 2) / KSTEP;  // 8 / 4 / 2

    __shared__ __half As[BM * SA];
    __shared__ __half Ws[N * SW];      // n-major, k-contiguous

    int tid = threadIdx.x;
    int lane = tid & 31, warp = tid >> 5;
    int wm = (warp & 1) * WM;
    int wn = (warp >> 1) * WN;
    int m0 = blockIdx.x * BM;
    int g = lane >> 2, tg = lane & 3;

    float acc[MT][NT][4] = {};

    // ---- loader addressing (constant across tiles) ----
    int a_r[2], a_c[2];                 // 2 chunks of 4 elements per thread
    #pragma unroll
    for (int i = 0; i < 2; i++) {
        int idx = tid + i * 256;
        a_r[i] = idx >> 3;              // row in tile
        a_c[i] = idx & 7;               // group-of-4 along k
    }
    int n_w = tid % N;                  // W loader: n fixed per thread
    int k2b = tid / N;

    // prefetch buffers
    float4 aRegF[2];
    uint2  aRegH[2];
    float2 wReg[WITER];

    // ---- prefetch tile 0 ----
    #pragma unroll
    for (int i = 0; i < 2; i++) {
        int m = m0 + a_r[i];
        if (A16) {
            aRegH[i] = make_uint2(0u, 0u);
            if (m < M)
                aRegH[i] = *reinterpret_cast<const uint2*>(
                    reinterpret_cast<const __half*>(A) + (size_t)m * K + a_c[i] * 4);
        } else {
            aRegF[i] = make_float4(0.f, 0.f, 0.f, 0.f);
            if (m < M)
                aRegF[i] = *reinterpret_cast<const float4*>(
                    reinterpret_cast<const float*>(A) + (size_t)m * K + a_c[i] * 4);
        }
    }
    #pragma unroll
    for (int i = 0; i < WITER; i++) {
        int k = 2 * (k2b + i * KSTEP);
        wReg[i] = make_float2(W[(size_t)k * N + n_w], W[(size_t)(k + 1) * N + n_w]);
    }

    for (int k0 = 0; k0 < K; k0 += BK) {
        // ---- commit prefetched regs -> smem ----
        #pragma unroll
        for (int i = 0; i < 2; i++) {
            uint2 u;
            if (A16) {
                u = aRegH[i];
            } else {
                __half2 p0 = __floats2half2_rn(aRegF[i].x, aRegF[i].y);
                __half2 p1 = __floats2half2_rn(aRegF[i].z, aRegF[i].w);
                u = make_uint2(*reinterpret_cast<unsigned*>(&p0),
                               *reinterpret_cast<unsigned*>(&p1));
            }
            *reinterpret_cast<uint2*>(As + a_r[i] * SA + a_c[i] * 4) = u;
        }
        #pragma unroll
        for (int i = 0; i < WITER; i++) {
            int k2 = k2b + i * KSTEP;
            *reinterpret_cast<__half2*>(Ws + n_w * SW + 2 * k2) =
                __floats2half2_rn(wReg[i].x, wReg[i].y);
        }
        __syncthreads();

        // ---- issue next tile's LDGs ----
        int kn = k0 + BK;
        if (kn < K) {
            #pragma unroll
            for (int i = 0; i < 2; i++) {
                int m = m0 + a_r[i];
                if (A16) {
                    aRegH[i] = make_uint2(0u, 0u);
                    if (m < M)
                        aRegH[i] = *reinterpret_cast<const uint2*>(
                            reinterpret_cast<const __half*>(A) + (size_t)m * K + kn + a_c[i] * 4);
                } else {
                    aRegF[i] = make_float4(0.f, 0.f, 0.f, 0.f);
                    if (m < M)
                        aRegF[i] = *reinterpret_cast<const float4*>(
                            reinterpret_cast<const float*>(A) + (size_t)m * K + kn + a_c[i] * 4);
                }
            }
            #pragma unroll
            for (int i = 0; i < WITER; i++) {
                int k = kn + 2 * (k2b + i * KSTEP);
                wReg[i] = make_float2(W[(size_t)k * N + n_w], W[(size_t)(k + 1) * N + n_w]);
            }
        }

        // ---- compute: 2 chunks of k16 ----
        #pragma unroll
        for (int kk = 0; kk < BK; kk += 16) {
            unsigned a[MT][4];
            #pragma unroll
            for (int mt = 0; mt < MT; mt++) {
                int base = (wm + mt * 16 + g) * SA + kk + tg * 2;
                a[mt][0] = *reinterpret_cast<const unsigned*>(As + base);
                a[mt][1] = *reinterpret_cast<const unsigned*>(As + base + 8 * SA);
                a[mt][2] = *reinterpret_cast<const unsigned*>(As + base + 8);
                a[mt][3] = *reinterpret_cast<const unsigned*>(As + base + 8 * SA + 8);
            }
            #pragma unroll
            for (int nt = 0; nt < NT; nt++) {
                int bb = (wn + nt * 8 + g) * SW + kk + tg * 2;
                unsigned b[2];
                b[0] = *reinterpret_cast<const unsigned*>(Ws + bb);
                b[1] = *reinterpret_cast<const unsigned*>(Ws + bb + 8);
                #pragma unroll
                for (int mt = 0; mt < MT; mt++)
                    mma_f16(acc[mt][nt], a[mt], b);
            }
        }
        __syncthreads();
    }

    // ---- epilogue: fp16 store ----
    #pragma unroll
    for (int mt = 0; mt < MT; mt++) {
        #pragma unroll
        for (int nt = 0; nt < NT; nt++) {
            int row0 = m0 + wm + mt * 16 + g;
            int col = wn + nt * 8 + 2 * tg;
            if (row0 < M)
                *reinterpret_cast<__half2*>(C + (size_t)row0 * N + col) =
                    __floats2half2_rn(acc[mt][nt][0], acc[mt][nt][1]);
            int row1 = row0 + 8;
            if (row1 < M)
                *reinterpret_cast<__half2*>(C + (size_t)row1 * N + col) =
                    __floats2half2_rn(acc[mt][nt][2], acc[mt][nt][3]);
        }
    }
}

// ---------------------------------------------------------------------------
// aggregation: warp per node; fp16 gathers, fp32 accumulate, OutT output
// ---------------------------------------------------------------------------
template <int VEC>
__device__ __forceinline__ void loadh(float* d, const __half* __restrict__ p) {
    if constexpr (VEC == 4) {
        uint2 raw = __ldg(reinterpret_cast<const uint2*>(p));
        float2 a = __half22float2(*reinterpret_cast<const __half2*>(&raw.x));
        float2 b = __half22float2(*reinterpret_cast<const __half2*>(&raw.y));
        d[0] = a.x; d[1] = a.y; d[2] = b.x; d[3] = b.y;
    } else if constexpr (VEC == 2) {
        __half2 h2 = __ldg(reinterpret_cast<const __half2*>(p));
        float2 a = __half22float2(h2);
        d[0] = a.x; d[1] = a.y;
    } else {
        d[0] = __half2float(__ldg(p));
    }
}

template <int F, bool RELU, typename OutT>
__launch_bounds__(256)
__global__ void k_agg(const __half* __restrict__ h, const float* __restrict__ bias,
                      OutT* __restrict__ out) {
    constexpr int VEC = F / 32;
    int node = (blockIdx.x * blockDim.x + threadIdx.x) >> 5;
    int lane = threadIdx.x & 31;
    if (node >= NN) return;

    float acc[VEC];
    {
        float d = g_dis[node];
        float ns = d * d;
        float t[VEC];
        loadh<VEC>(t, h + (size_t)node * F + lane * VEC);
        #pragma unroll
        for (int v = 0; v < VEC; v++) acc[v] = ns * t[v];
    }

    int start = g_off[node];
    int cnt   = g_cnt[node];
    int e = start, end = start + cnt;

    for (; e + 8 <= end; e += 8) {
        int   s[8];
        float nm[8];
        #pragma unroll
        for (int j = 0; j < 8; j++) { s[j] = g_esrc[e + j]; nm[j] = g_enorm[e + j]; }
        float t[8][VEC];
        #pragma unroll
        for (int j = 0; j < 8; j++)
            loadh<VEC>(t[j], h + (size_t)s[j] * F + lane * VEC);
        #pragma unroll
        for (int j = 0; j < 8; j++)
            #pragma unroll
            for (int v = 0; v < VEC; v++) acc[v] += nm[j] * t[j][v];
    }
    for (; e + 4 <= end; e += 4) {
        int   s[4];
        float nm[4];
        #pragma unroll
        for (int j = 0; j < 4; j++) { s[j] = g_esrc[e + j]; nm[j] = g_enorm[e + j]; }
        float t[4][VEC];
        #pragma unroll
        for (int j = 0; j < 4; j++)
            loadh<VEC>(t[j], h + (size_t)s[j] * F + lane * VEC);
        #pragma unroll
        for (int j = 0; j < 4; j++)
            #pragma unroll
            for (int v = 0; v < VEC; v++) acc[v] += nm[j] * t[j][v];
    }
    for (; e < end; e++) {
        int s0 = g_esrc[e];
        float nm = g_enorm[e];
        float t[VEC];
        loadh<VEC>(t, h + (size_t)s0 * F + lane * VEC);
        #pragma unroll
        for (int v = 0; v < VEC; v++) acc[v] += nm * t[v];
    }

    float res[VEC];
    #pragma unroll
    for (int v = 0; v < VEC; v++) {
        float r = acc[v] + bias[lane * VEC + v];
        if (RELU) r = fmaxf(r, 0.0f);
        res[v] = r;
    }

    if constexpr (sizeof(OutT) == 2) {
        __half* op = reinterpret_cast<__half*>(out) + (size_t)node * F + lane * VEC;
        if constexpr (VEC == 4) {
            __half2 p0 = __floats2half2_rn(res[0], res[1]);
            __half2 p1 = __floats2half2_rn(res[2], res[3]);
            *reinterpret_cast<uint2*>(op) =
                make_uint2(*reinterpret_cast<unsigned*>(&p0), *reinterpret_cast<unsigned*>(&p1));
        } else if constexpr (VEC == 2) {
            *reinterpret_cast<__half2*>(op) = __floats2half2_rn(res[0], res[1]);
        } else {
            *op = __float2half_rn(res[0]);
        }
    } else {
        float* op = reinterpret_cast<float*>(out) + (size_t)node * F + lane * VEC;
        if constexpr (VEC == 4)
            *reinterpret_cast<float4*>(op) = make_float4(res[0], res[1], res[2], res[3]);
        else if constexpr (VEC == 2)
            *reinterpret_cast<float2*>(op) = make_float2(res[0], res[1]);
        else
            *op = res[0];
    }
}

// ---------------------------------------------------------------------------
extern "C" void kernel_launch(void* const* d_in, const int* in_sizes, int n_in,
                              void* d_out, int out_size) {
    const float* x  = (const float*)d_in[0];
    const int*   ei = (const int*)d_in[1];
    const float* W1 = (const float*)d_in[2];
    const float* b1 = (const float*)d_in[3];
    const float* W2 = (const float*)d_in[4];
    const float* b2 = (const float*)d_in[5];
    const float* W3 = (const float*)d_in[6];
    const float* b3 = (const float*)d_in[7];

    int M = in_sizes[0] / IN_C;   // 100000
    int E = in_sizes[1] / 2;      // 1600000
    const int* row = ei;          // sources
    const int* col = ei + E;      // targets
    float* out = (float*)d_out;

    __half *gh, *ga;
    cudaGetSymbolAddress((void**)&gh, g_h);
    cudaGetSymbolAddress((void**)&ga, g_a);

    int nb1024 = (M + 1023) / 1024;
    int aggBlocks = (M + 7) / 8;
    int gemmBlocks = (M + 63) / 64;

    // gemm1 kept in launch slot 4 for the ncu window
    k_zero   <<<(M + 255) / 256, 256>>>(M);                            // 1
    k_count  <<<(E + 255) / 256, 256>>>(col, E);                       // 2
    k_scan1  <<<nb1024, 1024>>>(M);                                    // 3
    k_gemm<float, H1C, IN_C><<<gemmBlocks, 256>>>(x, W1, gh, M);       // 4 <- profiled
    k_scan2  <<<1, 32>>>(nb1024);                                      // 5
    k_scan3  <<<(M + 255) / 256, 256>>>(M);                            // 6
    k_scatter<<<(E + 255) / 256, 256>>>(row, col, E);                  // 7

    k_agg<H1C, true, __half><<<aggBlocks, 256>>>(gh, b1, ga);

    k_gemm<__half, H2C, H1C><<<gemmBlocks, 256>>>(ga, W2, gh, M);
    k_agg<H2C, true, __half><<<aggBlocks, 256>>>(gh, b2, ga);

    k_gemm<__half, OUTC, H2C><<<gemmBlocks, 256>>>(ga, W3, gh, M);
    k_agg<OUTC, false, float><<<aggBlocks, 256>>>(gh, b3, out);
}